// round 5
// baseline (speedup 1.0000x reference)
#include <cuda_runtime.h>
#include <cuda_bf16.h>
#include <cstdint>

// Problem constants (fixed by the reference)
#define PN   64      // batch
#define PL   2048    // sequence length
#define PC   256     // timestep channels
#define PDEM 10
#define PCO  276     // output channels = 256 + 20
#define SSEG 64      // segments along L
#define SEGL (PL / SSEG)   // 32

// Scratch (allocation-free: __device__ globals)
__device__ float g_dem_emb[PN * 20];
__device__ float g_recip[PL + 1];          // 1/max(k,1) for k = 0..2048
__device__ float g_prefix_sum[PN * SSEG * PC];
__device__ int   g_prefix_cnt[PN * SSEG * PC];
__device__ int   g_flags[PN * SSEG];

// ---------------------------------------------------------------------------
// Kernel 0: reset chain flags + reciprocal table + dem MLP
// (Linear 10->40, ReLU, 40->20, ReLU). Grid 16x256 = 4096 threads.
// ---------------------------------------------------------------------------
__global__ void prep_kernel(const float* __restrict__ dem,
                            const float* __restrict__ W1,
                            const float* __restrict__ b1,
                            const float* __restrict__ W2,
                            const float* __restrict__ b2) {
    int tid = blockIdx.x * blockDim.x + threadIdx.x;
    if (tid < PN * SSEG) g_flags[tid] = 0;
    if (tid <= PL) g_recip[tid] = 1.0f / (float)max(tid, 1);
    if (tid < PN) {
        float d[PDEM];
        #pragma unroll
        for (int k = 0; k < PDEM; k++) d[k] = dem[tid * PDEM + k];
        float h[40];
        #pragma unroll
        for (int j = 0; j < 40; j++) {
            float a = b1[j];
            #pragma unroll
            for (int k = 0; k < PDEM; k++) a = fmaf(d[k], W1[k * 40 + j], a);
            h[j] = fmaxf(a, 0.0f);
        }
        #pragma unroll
        for (int j = 0; j < 20; j++) {
            float a = b2[j];
            #pragma unroll
            for (int k = 0; k < 40; k++) a = fmaf(h[k], W2[k * 20 + j], a);
            g_dem_emb[tid * 20 + j] = fmaxf(a, 0.0f);
        }
    }
}

// ---------------------------------------------------------------------------
// Kernel 1: chained segmented scan, single DRAM read (segment staged in smem).
// Grid (SSEG, PN), 256 threads; thread t owns channel t of its (n, segment).
// Phase 1: stream segment (32 rows) into smem, accumulating (sum, count).
// Chain:   publish inclusive prefix, wait on predecessor via L2 flag.
// Phase 2: replay segment from smem, emit relu(cumsum * recip[cumcnt]).
// The 20 dem channels are constant along L -> coalesced epilogue store.
// ---------------------------------------------------------------------------
__global__ void __launch_bounds__(256)
scan_kernel(const float* __restrict__ ts, float* __restrict__ out) {
    const int s = blockIdx.x;       // segment
    const int n = blockIdx.y;       // patient
    const int t = threadIdx.x;      // channel 0..255

    __shared__ float s_data[SEGL * PC];   // 32 KB staged tile
    __shared__ float s_recip[PL + 1];     // 8.2 KB reciprocal table
    __shared__ float s_dem[20];

    // Fill smem reciprocal table + dem embedding (global copies are L2-hot)
    for (int k = t; k <= PL; k += 256) s_recip[k] = g_recip[k];
    if (t < 20) s_dem[t] = g_dem_emb[n * 20 + t];

    const float* base = ts + ((size_t)n * PL + (size_t)s * SEGL) * PC + t;

    // Phase 1: stream-in + local aggregate (evict-first: never re-read from L2)
    float sum = 0.0f;
    int   cnt = 0;
    #pragma unroll 8
    for (int i = 0; i < SEGL; i++) {
        float v = __ldcs(&base[(size_t)i * PC]);
        s_data[i * PC + t] = v;
        sum += v;
        cnt += (v != 0.0f) ? 1 : 0;
    }

    const int idx = n * SSEG + s;
    float pre_s = 0.0f;
    int   pre_c = 0;
    if (s > 0) {
        if (t == 0) {
            // predecessor has strictly smaller linear block id -> no deadlock
            volatile int* fl = &g_flags[idx - 1];
            while (*fl == 0) { __nanosleep(64); }
        }
        __syncthreads();
        __threadfence();
        pre_s = __ldcg(&g_prefix_sum[(idx - 1) * PC + t]);
        pre_c = __ldcg(&g_prefix_cnt[(idx - 1) * PC + t]);
    }
    if (s < SSEG - 1) {
        __stcg(&g_prefix_sum[idx * PC + t], pre_s + sum);
        __stcg(&g_prefix_cnt[idx * PC + t], pre_c + cnt);
        __threadfence();
        __syncthreads();   // all 256 channels published before flag set
        if (t == 0) atomicExch(&g_flags[idx], 1);
    }
    __syncthreads();       // smem tile + recip table ready before phase 2

    // Phase 2: replay from smem, division-free (LDS table lookup)
    float rs = pre_s;
    int   rc = pre_c;
    float* ob = out + ((size_t)n * PL + (size_t)s * SEGL) * PCO;
    #pragma unroll 4
    for (int i = 0; i < SEGL; i++) {
        float v = s_data[i * PC + t];
        rs += v;
        rc += (v != 0.0f) ? 1 : 0;
        float o = fmaxf(rs * s_recip[rc], 0.0f);
        ob[(size_t)i * PCO + t] = o;
    }

    // Epilogue: dem channels (constant along L, relu(const>=0)=const)
    for (int j = t; j < 20 * SEGL; j += 256) {
        int row = j / 20;
        int c   = j - row * 20;
        ob[(size_t)row * PCO + PC + c] = s_dem[c];
    }
}

// ---------------------------------------------------------------------------
// kernel_launch: prep (flags + table + dem MLP) then the chained scan.
// Graph-capturable, allocation-free, deterministic.
// Inputs (metadata order): timesteps(64,2048,256) f32, dem(64,10) f32,
//   W1(10,40) f32, b1(40) f32, W2(40,20) f32, b2(20) f32.
// Output: (64,2048,276) f32.
// ---------------------------------------------------------------------------
extern "C" void kernel_launch(void* const* d_in, const int* in_sizes, int n_in,
                              void* d_out, int out_size) {
    const float* ts  = (const float*)d_in[0];
    const float* dem = (const float*)d_in[1];
    const float* W1  = (const float*)d_in[2];
    const float* b1  = (const float*)d_in[3];
    const float* W2  = (const float*)d_in[4];
    const float* b2  = (const float*)d_in[5];
    float* out = (float*)d_out;

    prep_kernel<<<16, 256>>>(dem, W1, b1, W2, b2);
    dim3 grid(SSEG, PN);
    scan_kernel<<<grid, 256>>>(ts, out);
}

// round 7
// speedup vs baseline: 2.8876x; 2.8876x over previous
#include <cuda_runtime.h>
#include <cuda_bf16.h>
#include <cstdint>

// Problem constants (fixed by the reference)
#define PN   64      // batch
#define PL   2048    // sequence length
#define PC   256     // timestep channels
#define PDEM 10
#define PCO  276     // output channels = 256 + 20
#define SSEG 16      // segments along L  (grid = 1024 blocks -> fully resident)
#define SEGL (PL / SSEG)   // 128

// Scratch (allocation-free: __device__ globals)
__device__ float g_dem_emb[PN * 20];
__device__ float g_loc_sum[PN * SSEG * PC];   // per-(n,s) LOCAL aggregates
__device__ int   g_loc_cnt[PN * SSEG * PC];
__device__ int   g_flags[PN * SSEG];

// ---------------------------------------------------------------------------
// Kernel 0 (1 block): clear chain flags + dem MLP (10->40 ReLU -> 20 ReLU).
// ---------------------------------------------------------------------------
__global__ void prep_kernel(const float* __restrict__ dem,
                            const float* __restrict__ W1,
                            const float* __restrict__ b1,
                            const float* __restrict__ W2,
                            const float* __restrict__ b2) {
    int tid = threadIdx.x;
    #pragma unroll
    for (int k = tid; k < PN * SSEG; k += 256) g_flags[k] = 0;
    if (tid < PN) {
        float d[PDEM];
        #pragma unroll
        for (int k = 0; k < PDEM; k++) d[k] = dem[tid * PDEM + k];
        float h[40];
        #pragma unroll
        for (int j = 0; j < 40; j++) {
            float a = b1[j];
            #pragma unroll
            for (int k = 0; k < PDEM; k++) a = fmaf(d[k], W1[k * 40 + j], a);
            h[j] = fmaxf(a, 0.0f);
        }
        #pragma unroll
        for (int j = 0; j < 20; j++) {
            float a = b2[j];
            #pragma unroll
            for (int k = 0; k < 40; k++) a = fmaf(h[k], W2[k * 20 + j], a);
            g_dem_emb[tid * 20 + j] = fmaxf(a, 0.0f);
        }
    }
}

// ---------------------------------------------------------------------------
// Kernel 1: segmented scan with PARALLEL decoupled lookback.
// Grid (SSEG, PN), 256 threads; thread t owns channel t of its (n, segment).
// Phase 1: aggregate local (sum, nonzero-count) over 128 rows.
// Publish:  local aggregate + flag (no waiting first -> all publish ASAP).
// Lookback: poll all s predecessor flags in parallel (thread t polls flag t),
//           then sum their local aggregates (L2-hot) -> exclusive prefix.
// Phase 2: re-read segment (temporally close -> L2 hits), emit
//          relu(cumsum * recip[cumcnt]) via smem reciprocal table.
// ---------------------------------------------------------------------------
__global__ void __launch_bounds__(256)
scan_kernel(const float* __restrict__ ts, float* __restrict__ out) {
    const int s = blockIdx.x;       // segment
    const int n = blockIdx.y;       // patient
    const int t = threadIdx.x;      // channel 0..255

    __shared__ float s_recip[PL + 1];
    __shared__ float s_dem[20];

    // Build reciprocal table locally (8 divides/thread), fetch dem embedding
    for (int k = t; k <= PL; k += 256) s_recip[k] = 1.0f / (float)(k > 0 ? k : 1);
    if (t < 20) s_dem[t] = g_dem_emb[n * 20 + t];

    const float* base = ts + ((size_t)n * PL + (size_t)s * SEGL) * PC + t;

    // Phase 1: local aggregate
    float sum = 0.0f;
    int   cnt = 0;
    #pragma unroll 16
    for (int i = 0; i < SEGL; i++) {
        float v = base[(size_t)i * PC];
        sum += v;
        cnt += (v != 0.0f) ? 1 : 0;
    }

    const int idx = n * SSEG + s;

    // Publish local aggregate immediately (except the last segment: unused)
    if (s < SSEG - 1) {
        __stcg(&g_loc_sum[idx * PC + t], sum);
        __stcg(&g_loc_cnt[idx * PC + t], cnt);
        __threadfence();
        __syncthreads();   // all 256 channels published before flag set
        if (t == 0) atomicExch(&g_flags[idx], 1);
    }

    // Parallel lookback: wait for ALL predecessors at once, then sum aggregates
    float pre_s = 0.0f;
    int   pre_c = 0;
    if (s > 0) {
        if (t < s) {
            volatile int* fl = &g_flags[n * SSEG + t];
            while (*fl == 0) { __nanosleep(64); }
        }
        __syncthreads();
        __threadfence();
        #pragma unroll
        for (int j = 0; j < SSEG - 1; j++) {
            if (j < s) {
                pre_s += __ldcg(&g_loc_sum[(n * SSEG + j) * PC + t]);
                pre_c += __ldcg(&g_loc_cnt[(n * SSEG + j) * PC + t]);
            }
        }
    }
    __syncthreads();       // smem recip table ready before phase 2

    // Phase 2: re-read segment (temporally close -> L2 hits), division-free
    float rs = pre_s;
    int   rc = pre_c;
    float* ob = out + ((size_t)n * PL + (size_t)s * SEGL) * PCO;
    #pragma unroll 4
    for (int i = 0; i < SEGL; i++) {
        float v = __ldcs(&base[(size_t)i * PC]);
        rs += v;
        rc += (v != 0.0f) ? 1 : 0;
        float o = fmaxf(rs * s_recip[rc], 0.0f);
        ob[(size_t)i * PCO + t] = o;
    }

    // Epilogue: dem channels (constant along L, relu(const>=0)=const)
    for (int j = t; j < 20 * SEGL; j += 256) {
        int row = j / 20;
        int c   = j - row * 20;
        ob[(size_t)row * PCO + PC + c] = s_dem[c];
    }
}

// ---------------------------------------------------------------------------
// kernel_launch: prep (flags + dem MLP) then the lookback scan.
// Graph-capturable, allocation-free, deterministic.
// Inputs (metadata order): timesteps(64,2048,256) f32, dem(64,10) f32,
//   W1(10,40) f32, b1(40) f32, W2(40,20) f32, b2(20) f32.
// Output: (64,2048,276) f32.
// ---------------------------------------------------------------------------
extern "C" void kernel_launch(void* const* d_in, const int* in_sizes, int n_in,
                              void* d_out, int out_size) {
    const float* ts  = (const float*)d_in[0];
    const float* dem = (const float*)d_in[1];
    const float* W1  = (const float*)d_in[2];
    const float* b1  = (const float*)d_in[3];
    const float* W2  = (const float*)d_in[4];
    const float* b2  = (const float*)d_in[5];
    float* out = (float*)d_out;

    prep_kernel<<<1, 256>>>(dem, W1, b1, W2, b2);
    dim3 grid(SSEG, PN);
    scan_kernel<<<grid, 256>>>(ts, out);
}

// round 8
// speedup vs baseline: 3.4236x; 1.1856x over previous
#include <cuda_runtime.h>
#include <cuda_bf16.h>
#include <cstdint>

// Problem constants (fixed by the reference)
#define PN   64      // batch
#define PL   2048    // sequence length
#define PC   256     // timestep channels
#define PDEM 10
#define PCO  276     // output channels = 256 + 20
#define SSEG 16      // segments along L
#define SEGL (PL / SSEG)   // 128

// Scratch (allocation-free: __device__ globals)
__device__ float g_loc_sum[PN * SSEG * PC];   // per-(n,s) local aggregates
__device__ int   g_loc_cnt[PN * SSEG * PC];

// ---------------------------------------------------------------------------
// Kernel 1: per-segment aggregates, float4-vectorized, dependency-free.
// Grid (SSEG, PN), 256 threads. Thread t: quad q = t&63 (channels 4q..4q+3),
// row-phase p = t>>6 handles rows [32p, 32p+32). smem reduce across phases.
// ---------------------------------------------------------------------------
__global__ void __launch_bounds__(256)
agg_kernel(const float4* __restrict__ ts4) {
    const int s = blockIdx.x, n = blockIdx.y, t = threadIdx.x;
    const int p = t >> 6, q = t & 63;

    __shared__ float s_sum[4][PC];
    __shared__ int   s_cnt[4][PC];

    const float4* base =
        ts4 + ((size_t)(n * PL + s * SEGL + 32 * p)) * (PC / 4) + q;

    float4 a = make_float4(0.f, 0.f, 0.f, 0.f);
    int cx = 0, cy = 0, cz = 0, cw = 0;
    #pragma unroll 8
    for (int i = 0; i < 32; i++) {
        float4 v = __ldcs(&base[(size_t)i * (PC / 4)]);
        a.x += v.x; a.y += v.y; a.z += v.z; a.w += v.w;
        cx += (v.x != 0.f); cy += (v.y != 0.f);
        cz += (v.z != 0.f); cw += (v.w != 0.f);
    }
    s_sum[p][4 * q + 0] = a.x; s_sum[p][4 * q + 1] = a.y;
    s_sum[p][4 * q + 2] = a.z; s_sum[p][4 * q + 3] = a.w;
    s_cnt[p][4 * q + 0] = cx;  s_cnt[p][4 * q + 1] = cy;
    s_cnt[p][4 * q + 2] = cz;  s_cnt[p][4 * q + 3] = cw;
    __syncthreads();

    // Reduce phases in row order (p ascending) -> matches sequential grouping
    float S = ((s_sum[0][t] + s_sum[1][t]) + s_sum[2][t]) + s_sum[3][t];
    int   C = s_cnt[0][t] + s_cnt[1][t] + s_cnt[2][t] + s_cnt[3][t];
    const int idx = (n * SSEG + s) * PC + t;
    g_loc_sum[idx] = S;
    g_loc_cnt[idx] = C;
}

// ---------------------------------------------------------------------------
// Kernel 2: emit. Grid (SSEG, PN), 256 threads; thread t owns channel t.
// Self-contained: dem MLP + reciprocal table in smem (no prep kernel).
// Exclusive prefix = sum of predecessor aggregates (L2-hot, <=30 loads).
// Then stream segment -> relu(cumsum * recip[cumcnt]) -> output.
// ---------------------------------------------------------------------------
__global__ void __launch_bounds__(256)
emit_kernel(const float* __restrict__ ts,
            const float* __restrict__ dem,
            const float* __restrict__ W1,
            const float* __restrict__ b1,
            const float* __restrict__ W2,
            const float* __restrict__ b2,
            float* __restrict__ out) {
    const int s = blockIdx.x, n = blockIdx.y, t = threadIdx.x;

    __shared__ float s_recip[PL + 1];
    __shared__ float s_h[40];
    __shared__ float s_dem[20];

    // dem MLP layer 1 for this block's n (threads 0..39)
    if (t < 40) {
        float a = b1[t];
        #pragma unroll
        for (int k = 0; k < PDEM; k++) a = fmaf(dem[n * PDEM + k], W1[k * 40 + t], a);
        s_h[t] = fmaxf(a, 0.0f);
    }
    // Reciprocal table (8 divides per thread)
    for (int k = t; k <= PL; k += 256) s_recip[k] = 1.0f / (float)(k > 0 ? k : 1);
    __syncthreads();
    // Layer 2 (threads 0..19)
    if (t < 20) {
        float a = b2[t];
        #pragma unroll
        for (int k = 0; k < 40; k++) a = fmaf(s_h[k], W2[k * 20 + t], a);
        s_dem[t] = fmaxf(a, 0.0f);
    }

    // Exclusive prefix from predecessor aggregates (L2-hot)
    float pre_s = 0.0f;
    int   pre_c = 0;
    #pragma unroll
    for (int j = 0; j < SSEG - 1; j++) {
        if (j < s) {
            pre_s += g_loc_sum[(n * SSEG + j) * PC + t];
            pre_c += g_loc_cnt[(n * SSEG + j) * PC + t];
        }
    }
    __syncthreads();   // s_dem ready for epilogue; s_recip ready for loop

    // Stream segment -> output, division-free
    const float* base = ts + ((size_t)n * PL + (size_t)s * SEGL) * PC + t;
    float* ob = out + ((size_t)n * PL + (size_t)s * SEGL) * PCO;
    float rs = pre_s;
    int   rc = pre_c;
    #pragma unroll 8
    for (int i = 0; i < SEGL; i++) {
        float v = __ldcs(&base[(size_t)i * PC]);
        rs += v;
        rc += (v != 0.0f) ? 1 : 0;
        float o = fmaxf(rs * s_recip[rc], 0.0f);
        ob[(size_t)i * PCO + t] = o;
    }

    // Epilogue: dem channels (constant along L, relu(const>=0)=const)
    for (int j = t; j < 20 * SEGL; j += 256) {
        int row = j / 20;
        int c   = j - row * 20;
        ob[(size_t)row * PCO + PC + c] = s_dem[c];
    }
}

// ---------------------------------------------------------------------------
// kernel_launch: aggregate then emit; the kernel boundary is the only sync.
// Graph-capturable, allocation-free, deterministic (no persistent flags).
// Inputs (metadata order): timesteps(64,2048,256) f32, dem(64,10) f32,
//   W1(10,40) f32, b1(40) f32, W2(40,20) f32, b2(20) f32.
// Output: (64,2048,276) f32.
// ---------------------------------------------------------------------------
extern "C" void kernel_launch(void* const* d_in, const int* in_sizes, int n_in,
                              void* d_out, int out_size) {
    const float* ts  = (const float*)d_in[0];
    const float* dem = (const float*)d_in[1];
    const float* W1  = (const float*)d_in[2];
    const float* b1  = (const float*)d_in[3];
    const float* W2  = (const float*)d_in[4];
    const float* b2  = (const float*)d_in[5];
    float* out = (float*)d_out;

    dim3 grid(SSEG, PN);
    agg_kernel<<<grid, 256>>>((const float4*)ts);
    emit_kernel<<<grid, 256>>>(ts, dem, W1, b1, W2, b2, out);
}

// round 9
// speedup vs baseline: 4.1299x; 1.2063x over previous
#include <cuda_runtime.h>
#include <cuda_bf16.h>
#include <cstdint>

// Problem constants (fixed by the reference)
#define PN   64      // batch
#define PL   2048    // sequence length
#define PC   256     // timestep channels
#define PCQ  (PC / 4)       // 64 channel-quads
#define PDEM 10
#define PCO  276     // output channels = 256 + 20
#define PCOQ (PCO / 4)      // 69 output quads
#define SSEG 16      // segments along L
#define SEGL (PL / SSEG)    // 128
#define SUBL 32      // sub-segment rows (one row-phase)
#define NSUB 4       // sub-segments per segment

// Scratch (allocation-free __device__ globals, float4-aligned)
__device__ float4 g_sub_sum[PN * SSEG * NSUB * PCQ];  // [n][s*4+p][q]
__device__ float4 g_sub_cnt[PN * SSEG * NSUB * PCQ];
__device__ float4 g_seg_sum[PN * SSEG * PCQ];         // [n][s][q]
__device__ float4 g_seg_cnt[PN * SSEG * PCQ];

// ---------------------------------------------------------------------------
// Kernel 1: per-sub-segment + per-segment aggregates, float4, dependency-free.
// Grid (SSEG, PN), 256 threads. Thread t: quad q = t&63, phase p = t>>6
// handles rows [32p, 32p+32). Writes its sub-aggregate directly; smem reduce
// across phases produces the segment aggregate.
// ---------------------------------------------------------------------------
__global__ void __launch_bounds__(256)
agg_kernel(const float4* __restrict__ ts4) {
    const int s = blockIdx.x, n = blockIdx.y, t = threadIdx.x;
    const int p = t >> 6, q = t & 63;

    __shared__ float s_sum[NSUB][PC];
    __shared__ float s_cnt[NSUB][PC];

    const float4* base = ts4 + ((size_t)(n * PL + s * SEGL + SUBL * p)) * PCQ + q;

    float4 a = make_float4(0.f, 0.f, 0.f, 0.f);
    float4 c = make_float4(0.f, 0.f, 0.f, 0.f);
    #pragma unroll 8
    for (int i = 0; i < SUBL; i++) {
        float4 v = __ldcs(&base[(size_t)i * PCQ]);
        a.x += v.x; a.y += v.y; a.z += v.z; a.w += v.w;
        c.x += (v.x != 0.f) ? 1.f : 0.f;
        c.y += (v.y != 0.f) ? 1.f : 0.f;
        c.z += (v.z != 0.f) ? 1.f : 0.f;
        c.w += (v.w != 0.f) ? 1.f : 0.f;
    }

    // Sub-aggregate (float4, coalesced)
    const int sub_idx = ((n * SSEG + s) * NSUB + p) * PCQ + q;
    g_sub_sum[sub_idx] = a;
    g_sub_cnt[sub_idx] = c;

    // Cross-phase reduce for the segment aggregate
    s_sum[p][4 * q + 0] = a.x; s_sum[p][4 * q + 1] = a.y;
    s_sum[p][4 * q + 2] = a.z; s_sum[p][4 * q + 3] = a.w;
    s_cnt[p][4 * q + 0] = c.x; s_cnt[p][4 * q + 1] = c.y;
    s_cnt[p][4 * q + 2] = c.z; s_cnt[p][4 * q + 3] = c.w;
    __syncthreads();

    float S = ((s_sum[0][t] + s_sum[1][t]) + s_sum[2][t]) + s_sum[3][t];
    float C = ((s_cnt[0][t] + s_cnt[1][t]) + s_cnt[2][t]) + s_cnt[3][t];
    const int seg_base = (n * SSEG + s) * PCQ;
    ((float*)&g_seg_sum[seg_base])[t] = S;
    ((float*)&g_seg_cnt[seg_base])[t] = C;
}

// ---------------------------------------------------------------------------
// Kernel 2: emit, fully float4. Grid (SSEG, PN), 256 threads.
// Thread t: quad q = t&63 (channels 4q..4q+3), phase p = t>>6 (rows 32p..+32).
// Two-level lookback: <=15 segment aggregates + <=3 sub aggregates (L2-hot).
// Scan 32 rows: LDG.128 -> FADDs -> MUFU rcp -> STG.128. Dem epilogue float4.
// ---------------------------------------------------------------------------
__global__ void __launch_bounds__(256)
emit_kernel(const float4* __restrict__ ts4,
            const float* __restrict__ dem,
            const float* __restrict__ W1,
            const float* __restrict__ b1,
            const float* __restrict__ W2,
            const float* __restrict__ b2,
            float4* __restrict__ out4) {
    const int s = blockIdx.x, n = blockIdx.y, t = threadIdx.x;
    const int p = t >> 6, q = t & 63;

    __shared__ float  s_h[40];
    __shared__ float4 s_dem4[5];   // 20 dem channels as 5 float4

    // dem MLP layer 1 (threads 0..39)
    if (t < 40) {
        float a = b1[t];
        #pragma unroll
        for (int k = 0; k < PDEM; k++)
            a = fmaf(dem[n * PDEM + k], W1[k * 40 + t], a);
        s_h[t] = fmaxf(a, 0.0f);
    }
    __syncthreads();
    // Layer 2 (threads 0..19); relu(const>=0)=const along L
    if (t < 20) {
        float a = b2[t];
        #pragma unroll
        for (int k = 0; k < 40; k++) a = fmaf(s_h[k], W2[k * 20 + t], a);
        ((float*)s_dem4)[t] = fmaxf(a, 0.0f);
    }

    // Two-level lookback (independent of smem; overlaps with MLP latency)
    float4 ps = make_float4(0.f, 0.f, 0.f, 0.f);
    float4 pc = make_float4(0.f, 0.f, 0.f, 0.f);
    #pragma unroll
    for (int j = 0; j < SSEG - 1; j++) {
        if (j < s) {
            float4 a = g_seg_sum[(n * SSEG + j) * PCQ + q];
            float4 c = g_seg_cnt[(n * SSEG + j) * PCQ + q];
            ps.x += a.x; ps.y += a.y; ps.z += a.z; ps.w += a.w;
            pc.x += c.x; pc.y += c.y; pc.z += c.z; pc.w += c.w;
        }
    }
    #pragma unroll
    for (int k = 0; k < NSUB - 1; k++) {
        if (k < p) {
            float4 a = g_sub_sum[((n * SSEG + s) * NSUB + k) * PCQ + q];
            float4 c = g_sub_cnt[((n * SSEG + s) * NSUB + k) * PCQ + q];
            ps.x += a.x; ps.y += a.y; ps.z += a.z; ps.w += a.w;
            pc.x += c.x; pc.y += c.y; pc.z += c.z; pc.w += c.w;
        }
    }
    __syncthreads();   // s_dem4 ready for epilogue

    // Scan this phase's 32 rows, division via fast MUFU reciprocal
    const int row0 = s * SEGL + SUBL * p;
    const float4* base = ts4 + ((size_t)(n * PL + row0)) * PCQ + q;
    float4* ob = out4 + ((size_t)(n * PL + row0)) * PCOQ + q;

    float4 rs = ps, rc = pc;
    #pragma unroll 8
    for (int i = 0; i < SUBL; i++) {
        float4 v = __ldcs(&base[(size_t)i * PCQ]);
        rs.x += v.x; rc.x += (v.x != 0.f) ? 1.f : 0.f;
        rs.y += v.y; rc.y += (v.y != 0.f) ? 1.f : 0.f;
        rs.z += v.z; rc.z += (v.z != 0.f) ? 1.f : 0.f;
        rs.w += v.w; rc.w += (v.w != 0.f) ? 1.f : 0.f;
        float4 o;
        o.x = fmaxf(__fdividef(rs.x, fmaxf(rc.x, 1.f)), 0.f);
        o.y = fmaxf(__fdividef(rs.y, fmaxf(rc.y, 1.f)), 0.f);
        o.z = fmaxf(__fdividef(rs.z, fmaxf(rc.z, 1.f)), 0.f);
        o.w = fmaxf(__fdividef(rs.w, fmaxf(rc.w, 1.f)), 0.f);
        __stcs(&ob[(size_t)i * PCOQ], o);
    }

    // Epilogue: dem channels for all 128 rows of this segment (float4 stores)
    float4* obseg = out4 + ((size_t)(n * PL + s * SEGL)) * PCOQ;
    #pragma unroll
    for (int j = t; j < SEGL * 5; j += 256) {
        int row = j / 5;
        int c   = j - row * 5;
        __stcs(&obseg[(size_t)row * PCOQ + PCQ + c], s_dem4[c]);
    }
}

// ---------------------------------------------------------------------------
// kernel_launch: aggregate then emit; kernel boundary is the only sync.
// Graph-capturable, allocation-free, deterministic (no persistent flags).
// Inputs (metadata order): timesteps(64,2048,256) f32, dem(64,10) f32,
//   W1(10,40) f32, b1(40) f32, W2(40,20) f32, b2(20) f32.
// Output: (64,2048,276) f32.
// ---------------------------------------------------------------------------
extern "C" void kernel_launch(void* const* d_in, const int* in_sizes, int n_in,
                              void* d_out, int out_size) {
    const float* ts  = (const float*)d_in[0];
    const float* dem = (const float*)d_in[1];
    const float* W1  = (const float*)d_in[2];
    const float* b1  = (const float*)d_in[3];
    const float* W2  = (const float*)d_in[4];
    const float* b2  = (const float*)d_in[5];
    float* out = (float*)d_out;

    dim3 grid(SSEG, PN);
    agg_kernel<<<grid, 256>>>((const float4*)ts);
    emit_kernel<<<grid, 256>>>((const float4*)ts, dem, W1, b1, W2, b2,
                               (float4*)out);
}

// round 10
// speedup vs baseline: 4.4910x; 1.0874x over previous
#include <cuda_runtime.h>
#include <cuda_bf16.h>
#include <cstdint>

// Problem constants (fixed by the reference)
#define PN   64      // batch
#define PL   2048    // sequence length
#define PC   256     // timestep channels
#define PCQ  (PC / 4)       // 64 channel-quads
#define PDEM 10
#define PCO  276     // output channels = 256 + 20
#define PCOQ (PCO / 4)      // 69 output quads
#define SSEG 16      // segments along L
#define SEGL (PL / SSEG)    // 128
#define SUBL 32      // sub-segment rows (one row-phase)
#define NSUB 4       // sub-segments per segment

// Scratch (allocation-free __device__ globals, float4-aligned)
__device__ float4 g_sub_sum[PN * SSEG * NSUB * PCQ];  // [n][s*4+p][q]
__device__ float4 g_sub_cnt[PN * SSEG * NSUB * PCQ];
__device__ float4 g_seg_sum[PN * SSEG * PCQ];         // [n][s][q]
__device__ float4 g_seg_cnt[PN * SSEG * PCQ];

// ---------------------------------------------------------------------------
// Kernel 1: aggregates + dem MLP + dem-column output.
// Grid (SSEG, PN), 256 threads. Thread t: quad q = t&63, phase p = t>>6
// handles rows [32p, 32p+32), read in REVERSE order with L2-allocating loads
// so the last-touched rows (low i) are L2-hot when emit reads them first.
// Also computes the dem MLP (redundant per block, trivially cheap) and writes
// the 20 constant dem output channels for this segment's 128 rows.
// ---------------------------------------------------------------------------
__global__ void __launch_bounds__(256)
agg_kernel(const float4* __restrict__ ts4,
           const float* __restrict__ dem,
           const float* __restrict__ W1,
           const float* __restrict__ b1,
           const float* __restrict__ W2,
           const float* __restrict__ b2,
           float4* __restrict__ out4) {
    const int s = blockIdx.x, n = blockIdx.y, t = threadIdx.x;
    const int p = t >> 6, q = t & 63;

    __shared__ float  s_sum[NSUB][PC];
    __shared__ float  s_cnt[NSUB][PC];
    __shared__ float  s_h[40];
    __shared__ float4 s_dem4[5];   // 20 dem channels as 5 float4

    const float4* base = ts4 + ((size_t)(n * PL + s * SEGL + SUBL * p)) * PCQ + q;

    // Main aggregate, rows in reverse (sum is order-independent)
    float4 a = make_float4(0.f, 0.f, 0.f, 0.f);
    float4 c = make_float4(0.f, 0.f, 0.f, 0.f);
    #pragma unroll 8
    for (int i = SUBL - 1; i >= 0; i--) {
        float4 v = __ldcg(&base[(size_t)i * PCQ]);
        a.x += v.x; a.y += v.y; a.z += v.z; a.w += v.w;
        c.x += (v.x != 0.f) ? 1.f : 0.f;
        c.y += (v.y != 0.f) ? 1.f : 0.f;
        c.z += (v.z != 0.f) ? 1.f : 0.f;
        c.w += (v.w != 0.f) ? 1.f : 0.f;
    }

    // Sub-aggregate (float4, coalesced)
    const int sub_idx = ((n * SSEG + s) * NSUB + p) * PCQ + q;
    g_sub_sum[sub_idx] = a;
    g_sub_cnt[sub_idx] = c;

    // dem MLP layer 1 (threads 0..39)
    if (t < 40) {
        float acc = b1[t];
        #pragma unroll
        for (int k = 0; k < PDEM; k++)
            acc = fmaf(dem[n * PDEM + k], W1[k * 40 + t], acc);
        s_h[t] = fmaxf(acc, 0.0f);
    }

    // Cross-phase reduce for the segment aggregate
    s_sum[p][4 * q + 0] = a.x; s_sum[p][4 * q + 1] = a.y;
    s_sum[p][4 * q + 2] = a.z; s_sum[p][4 * q + 3] = a.w;
    s_cnt[p][4 * q + 0] = c.x; s_cnt[p][4 * q + 1] = c.y;
    s_cnt[p][4 * q + 2] = c.z; s_cnt[p][4 * q + 3] = c.w;
    __syncthreads();

    // dem MLP layer 2 (threads 0..19); relu(const>=0)=const along L
    if (t < 20) {
        float acc = b2[t];
        #pragma unroll
        for (int k = 0; k < 40; k++) acc = fmaf(s_h[k], W2[k * 20 + t], acc);
        ((float*)s_dem4)[t] = fmaxf(acc, 0.0f);
    }

    float S = ((s_sum[0][t] + s_sum[1][t]) + s_sum[2][t]) + s_sum[3][t];
    float C = ((s_cnt[0][t] + s_cnt[1][t]) + s_cnt[2][t]) + s_cnt[3][t];
    const int seg_base = (n * SSEG + s) * PCQ;
    ((float*)&g_seg_sum[seg_base])[t] = S;
    ((float*)&g_seg_cnt[seg_base])[t] = C;
    __syncthreads();   // s_dem4 ready

    // dem-column output for this segment's 128 rows (5 float4 per row)
    float4* obseg = out4 + ((size_t)(n * PL + s * SEGL)) * PCOQ;
    #pragma unroll
    for (int j = t; j < SEGL * 5; j += 256) {
        int row = j / 5;
        int cc  = j - row * 5;
        __stcs(&obseg[(size_t)row * PCOQ + PCQ + cc], s_dem4[cc]);
    }
}

// ---------------------------------------------------------------------------
// Kernel 2: emit — sync-free, smem-free pure stream.
// Grid (SSEG, PN), 256 threads. Thread t: quad q = t&63, phase p = t>>6.
// Two-level lookback (L2-hot aggregates), then scan 32 rows:
// LDG.128(evict-first) -> FADDs -> MUFU rcp -> STG.128(streaming).
// ---------------------------------------------------------------------------
__global__ void __launch_bounds__(256)
emit_kernel(const float4* __restrict__ ts4, float4* __restrict__ out4) {
    const int s = blockIdx.x, n = blockIdx.y, t = threadIdx.x;
    const int p = t >> 6, q = t & 63;

    // Two-level lookback
    float4 ps = make_float4(0.f, 0.f, 0.f, 0.f);
    float4 pc = make_float4(0.f, 0.f, 0.f, 0.f);
    #pragma unroll
    for (int j = 0; j < SSEG - 1; j++) {
        if (j < s) {
            float4 a = g_seg_sum[(n * SSEG + j) * PCQ + q];
            float4 c = g_seg_cnt[(n * SSEG + j) * PCQ + q];
            ps.x += a.x; ps.y += a.y; ps.z += a.z; ps.w += a.w;
            pc.x += c.x; pc.y += c.y; pc.z += c.z; pc.w += c.w;
        }
    }
    #pragma unroll
    for (int k = 0; k < NSUB - 1; k++) {
        if (k < p) {
            float4 a = g_sub_sum[((n * SSEG + s) * NSUB + k) * PCQ + q];
            float4 c = g_sub_cnt[((n * SSEG + s) * NSUB + k) * PCQ + q];
            ps.x += a.x; ps.y += a.y; ps.z += a.z; ps.w += a.w;
            pc.x += c.x; pc.y += c.y; pc.z += c.z; pc.w += c.w;
        }
    }

    // Scan this phase's 32 rows
    const int row0 = s * SEGL + SUBL * p;
    const float4* base = ts4 + ((size_t)(n * PL + row0)) * PCQ + q;
    float4* ob = out4 + ((size_t)(n * PL + row0)) * PCOQ + q;

    float4 rs = ps, rc = pc;
    #pragma unroll 8
    for (int i = 0; i < SUBL; i++) {
        float4 v = __ldcs(&base[(size_t)i * PCQ]);
        rs.x += v.x; rc.x += (v.x != 0.f) ? 1.f : 0.f;
        rs.y += v.y; rc.y += (v.y != 0.f) ? 1.f : 0.f;
        rs.z += v.z; rc.z += (v.z != 0.f) ? 1.f : 0.f;
        rs.w += v.w; rc.w += (v.w != 0.f) ? 1.f : 0.f;
        float4 o;
        o.x = fmaxf(__fdividef(rs.x, fmaxf(rc.x, 1.f)), 0.f);
        o.y = fmaxf(__fdividef(rs.y, fmaxf(rc.y, 1.f)), 0.f);
        o.z = fmaxf(__fdividef(rs.z, fmaxf(rc.z, 1.f)), 0.f);
        o.w = fmaxf(__fdividef(rs.w, fmaxf(rc.w, 1.f)), 0.f);
        __stcs(&ob[(size_t)i * PCOQ], o);
    }
}

// ---------------------------------------------------------------------------
// kernel_launch: aggregate(+dem) then emit; kernel boundary is the only sync.
// Graph-capturable, allocation-free, deterministic (no persistent flags).
// Inputs (metadata order): timesteps(64,2048,256) f32, dem(64,10) f32,
//   W1(10,40) f32, b1(40) f32, W2(40,20) f32, b2(20) f32.
// Output: (64,2048,276) f32.
// ---------------------------------------------------------------------------
extern "C" void kernel_launch(void* const* d_in, const int* in_sizes, int n_in,
                              void* d_out, int out_size) {
    const float* ts  = (const float*)d_in[0];
    const float* dem = (const float*)d_in[1];
    const float* W1  = (const float*)d_in[2];
    const float* b1  = (const float*)d_in[3];
    const float* W2  = (const float*)d_in[4];
    const float* b2  = (const float*)d_in[5];
    float* out = (float*)d_out;

    dim3 grid(SSEG, PN);
    agg_kernel<<<grid, 256>>>((const float4*)ts, dem, W1, b1, W2, b2,
                              (float4*)out);
    emit_kernel<<<grid, 256>>>((const float4*)ts, (float4*)out);
}